// round 4
// baseline (speedup 1.0000x reference)
#include <cuda_runtime.h>
#include <cuda_bf16.h>
#include <math.h>

// Problem: result[b] = sigmoid( u^T X_b v + bias ),  u = basis^T w_h, v = basis^T w_v
// N = 512, BATCH = 256. x is (256, 512*512) fp32. Output (256,1) fp32.

#define NN 512
#define BATCH 256
#define CHUNKS 8                       // chunks per batch in main kernel
#define CHUNK_F4 8192                  // float4s per chunk (32768 floats)

__device__ __align__(16) float g_u[NN];
__device__ __align__(16) float g_v[NN];
__device__ float g_partial[BATCH * CHUNKS];

// ---------------------------------------------------------------------------
// Kernel 1: u[k] = sum_i w_h[i] * cu[i] * cos((2k+1) i pi / (2N)), same for v.
// One block per k (512 blocks), 512 threads (one per i). Exact integer phase
// reduction mod 4N keeps cosf argument in [0, 2pi).
// ---------------------------------------------------------------------------
__global__ void dct_prep(const float* __restrict__ wh, const float* __restrict__ wv) {
    const int k = blockIdx.x;
    const int i = threadIdx.x;

    // cu[0] = sqrt(1/512), cu[i>0] = sqrt(2/512) = 1/16
    const float cu = (i == 0) ? 0.04419417382415922f : 0.0625f;
    const int m = ((2 * k + 1) * i) & 2047;                 // mod 4N
    const float ang = (float)m * 0.0030679615757712823f;    // * pi/1024
    const float c = cu * cosf(ang);

    float tu = wh[i] * c;
    float tv = wv[i] * c;

    // warp reduce
    #pragma unroll
    for (int o = 16; o; o >>= 1) {
        tu += __shfl_down_sync(0xffffffffu, tu, o);
        tv += __shfl_down_sync(0xffffffffu, tv, o);
    }
    __shared__ float su[16], sv[16];
    const int w = i >> 5, lane = i & 31;
    if (lane == 0) { su[w] = tu; sv[w] = tv; }
    __syncthreads();
    if (w == 0) {
        tu = (lane < 16) ? su[lane] : 0.0f;
        tv = (lane < 16) ? sv[lane] : 0.0f;
        #pragma unroll
        for (int o = 8; o; o >>= 1) {
            tu += __shfl_down_sync(0xffffffffu, tu, o);
            tv += __shfl_down_sync(0xffffffffu, tv, o);
        }
        if (lane == 0) { g_u[k] = tu; g_v[k] = tv; }
    }
}

// ---------------------------------------------------------------------------
// Kernel 2: partial[b, chunk] = sum over 32768 elements of x[b] * u[k]*v[l].
// grid = (CHUNKS, BATCH), 256 threads. float4 global loads; v kept in shared
// as float4 (conflict-free LDS.128); u constant per warp-iteration (broadcast).
// No atomics -> bitwise deterministic across graph replays.
// ---------------------------------------------------------------------------
__global__ __launch_bounds__(256) void dct_main(const float* __restrict__ x) {
    __shared__ float4 sv4[NN / 4];   // all 512 v values
    __shared__ float su[64];         // 64 u values covered by this chunk
    __shared__ float sred[8];

    const int t = threadIdx.x;
    const int chunk = blockIdx.x;
    const int b = blockIdx.y;

    if (t < 128) sv4[t] = reinterpret_cast<const float4*>(g_v)[t];
    if (t >= 128 && t < 192) su[t - 128] = g_u[chunk * 64 + (t - 128)];
    __syncthreads();

    const float4* xp = reinterpret_cast<const float4*>(x)
                     + ((size_t)b << 16) + ((size_t)chunk << 13);

    float sum = 0.0f;
    #pragma unroll 16
    for (int i = t; i < CHUNK_F4; i += 256) {
        const float4 xv = __ldg(xp + i);
        const float4 vv = sv4[i & 127];      // l-group = i mod 128
        const float uk = su[i >> 7];         // k-row within chunk (warp-uniform)
        sum += uk * (xv.x * vv.x + xv.y * vv.y + xv.z * vv.z + xv.w * vv.w);
    }

    // block reduce 256 -> 1
    #pragma unroll
    for (int o = 16; o; o >>= 1) sum += __shfl_down_sync(0xffffffffu, sum, o);
    if ((t & 31) == 0) sred[t >> 5] = sum;
    __syncthreads();
    if (t < 8) {
        sum = sred[t];
        #pragma unroll
        for (int o = 4; o; o >>= 1) sum += __shfl_down_sync(0x000000ffu, sum, o);
        if (t == 0) g_partial[b * CHUNKS + chunk] = sum;
    }
}

// ---------------------------------------------------------------------------
// Kernel 3: out[b] = sigmoid(sum_c partial[b,c] + bias). Fixed summation order.
// ---------------------------------------------------------------------------
__global__ void dct_fin(const float* __restrict__ bias, float* __restrict__ out) {
    const int b = threadIdx.x;   // 256 threads, 1 block
    float s = 0.0f;
    #pragma unroll
    for (int c = 0; c < CHUNKS; ++c) s += g_partial[b * CHUNKS + c];
    s += bias[0];
    out[b] = 1.0f / (1.0f + expf(-s));
}

extern "C" void kernel_launch(void* const* d_in, const int* in_sizes, int n_in,
                              void* d_out, int out_size) {
    const float* x    = (const float*)d_in[0];
    const float* wh   = (const float*)d_in[1];
    const float* wv   = (const float*)d_in[2];
    const float* bias = (const float*)d_in[3];
    float* out = (float*)d_out;

    dct_prep<<<NN, NN>>>(wh, wv);
    dim3 grid(CHUNKS, BATCH);
    dct_main<<<grid, 256>>>(x);
    dct_fin<<<1, BATCH>>>(bias, out);
}